// round 16
// baseline (speedup 1.0000x reference)
#include <cuda_runtime.h>
#include <cuda_bf16.h>
#include <cuda_fp16.h>
#include <math.h>
#include <stdint.h>

// Problem constants
#define B_SZ 2
#define S_LEN 2048
#define E_DIM 1024
#define H_NUM 16
#define D_HEAD 64
#define M_ROWS (B_SZ * S_LEN)        // 4096
#define ATTN_SCALE 0.03125f          // 1/sqrt(1024)
#define LOG2E 1.4426950408889634f
#define SCALE2 (ATTN_SCALE * LOG2E)  // base-2 softmax scale
#define MOFF 4.0f                    // fixed softmax offset

// ---------------- scratch (device globals: no allocation allowed) ----------
__device__ __half g_x16[M_ROWS * E_DIM];
__device__ __half g_wqkv16[3 * E_DIM * E_DIM];   // concat [Wq; Wk; Wv]
__device__ __half g_wo16[E_DIM * E_DIM];
__device__ __half g_q16[M_ROWS * E_DIM];
__device__ __half g_k16[M_ROWS * E_DIM];
__device__ __half g_v16[M_ROWS * E_DIM];
__device__ __half g_a16[M_ROWS * E_DIM];
__device__ float2 g_tab[S_LEN * 32];               // rope cos/sin table

// ============================ PTX helpers (sm_80-era only) =================
__device__ __forceinline__ uint32_t smem_u32(const void* p) {
    uint32_t a;
    asm("{ .reg .u64 t; cvta.to.shared.u64 t, %1; cvt.u32.u64 %0, t; }"
        : "=r"(a) : "l"(p));
    return a;
}
#define CP_ASYNC16(dst, src) \
    asm volatile("cp.async.cg.shared.global [%0], [%1], 16;" \
                 :: "r"(dst), "l"(src))
#define CP_COMMIT() asm volatile("cp.async.commit_group;")
#define CP_WAIT(n)  asm volatile("cp.async.wait_group %0;" :: "n"(n))

__device__ __forceinline__ void ldm_x4(uint32_t* r, uint32_t addr) {
    asm volatile("ldmatrix.sync.aligned.x4.m8n8.shared.b16 {%0,%1,%2,%3}, [%4];"
                 : "=r"(r[0]), "=r"(r[1]), "=r"(r[2]), "=r"(r[3]) : "r"(addr));
}
__device__ __forceinline__ void ldm_x4_t(uint32_t* r, uint32_t addr) {
    asm volatile("ldmatrix.sync.aligned.x4.m8n8.trans.shared.b16 {%0,%1,%2,%3}, [%4];"
                 : "=r"(r[0]), "=r"(r[1]), "=r"(r[2]), "=r"(r[3]) : "r"(addr));
}
__device__ __forceinline__ void mma_f16(float* d, const uint32_t* a,
                                        const uint32_t* b) {
    asm volatile(
        "mma.sync.aligned.m16n8k16.row.col.f32.f16.f16.f32 "
        "{%0,%1,%2,%3}, {%4,%5,%6,%7}, {%8,%9}, {%0,%1,%2,%3};"
        : "+f"(d[0]), "+f"(d[1]), "+f"(d[2]), "+f"(d[3])
        : "r"(a[0]), "r"(a[1]), "r"(a[2]), "r"(a[3]), "r"(b[0]), "r"(b[1]));
}
__device__ __forceinline__ uint32_t f22h(float a, float b) {
    __half2 h = __floats2half2_rn(a, b);
    return *(uint32_t*)&h;
}
// guaranteed single-MUFU exponential (base 2), f32
__device__ __forceinline__ float ex2(float x) {
    float r;
    asm("ex2.approx.ftz.f32 %0, %1;" : "=f"(r) : "f"(x));
    return r;
}

// ============================ fused prep kernel ============================
// blocks [0, 2048)           : convert x -> f16            (4M elems)
// blocks [2048, 4096)        : convert Wq/Wk/Wv/Wo -> f16  (4 x 1M elems)
// blocks [4096, 4352)        : rope cos/sin table (fp64)   (64K entries)
__global__ __launch_bounds__(256) void prep_all(
    const float4* __restrict__ x,
    const float4* __restrict__ wq, const float4* __restrict__ wk,
    const float4* __restrict__ wv, const float4* __restrict__ wo,
    uint4* __restrict__ ox, uint4* __restrict__ oqkv, uint4* __restrict__ oo,
    float2* __restrict__ tab) {
    int bid = blockIdx.x;
    if (bid < 2048) {                  // x convert
        int idx = bid * 256 + threadIdx.x;
        float4 a = x[2 * idx], b = x[2 * idx + 1];
        uint4 o;
        o.x = f22h(a.x, a.y); o.y = f22h(a.z, a.w);
        o.z = f22h(b.x, b.y); o.w = f22h(b.z, b.w);
        ox[idx] = o;
    } else if (bid < 4096) {           // weight converts
        int idx = (bid - 2048) * 256 + threadIdx.x;   // 4 * 131072
        int sel = idx >> 17;
        int j = idx & 131071;
        const float4* in = (sel == 0) ? wq : (sel == 1) ? wk : (sel == 2) ? wv : wo;
        uint4* out = (sel == 3) ? oo : (oqkv + (size_t)sel * 131072);
        float4 a = in[2 * j], b = in[2 * j + 1];
        uint4 o;
        o.x = f22h(a.x, a.y); o.y = f22h(a.z, a.w);
        o.z = f22h(b.x, b.y); o.w = f22h(b.z, b.w);
        out[j] = o;
    } else {                           // rope table
        int idx = (bid - 4096) * 256 + threadIdx.x;   // 65536
        int s = idx >> 5, i = idx & 31;
        double inv = exp(-((double)(2 * i) / 64.0) * log(10000.0));
        double cd, sd;
        sincos((double)s * inv, &sd, &cd);
        tab[idx] = make_float2((float)cd, (float)sd);
    }
}

// ============================ mma.sync GEMM (R9 calibrated core) ===========
// 128x128 CTA tile, BK=32, 8 warps of 32(M)x64(N), 3-stage cp.async,
// CP_WAIT(1).  MODE 3: QKV fused (f16 + RoPE), MODE 2: f32 out.
#define GPITCH 80
#define STAGE_BYTES (2 * 128 * GPITCH)       // 20480
#define SMEM_B_REL (128 * GPITCH)            // 10240
#define GSMEM (3 * STAGE_BYTES)              // 61440
#define GK4 128                              // uint4 per row (K=1024)

template <int MODE>
__global__ __launch_bounds__(256, 2) void gemm_mma(const void* __restrict__ Av,
                                                   const void* __restrict__ Bv,
                                                   void* __restrict__ Y0,
                                                   void* __restrict__ Y1,
                                                   void* __restrict__ Y2,
                                                   const float2* __restrict__ tab) {
    extern __shared__ __align__(16) char smbuf[];
    const uint32_t sb = smem_u32(smbuf);

    const int tid = threadIdx.x;
    const int wid = tid >> 5, lane = tid & 31;
    const int wm = wid & 3, wn = wid >> 2;
    const int mb = blockIdx.y * 128, nb = blockIdx.x * 128;

    const int lrow = tid >> 2;
    const int lkv = tid & 3;

    float acc[2][8][4];
#pragma unroll
    for (int i = 0; i < 2; i++)
#pragma unroll
        for (int j = 0; j < 8; j++)
#pragma unroll
            for (int q = 0; q < 4; q++) acc[i][j][q] = 0.f;

    const uint4* gA = (const uint4*)Av;
    const uint4* gB = (const uint4*)Bv;

    auto load_chunk = [&](int c, int s) {
        uint32_t sbase = sb + s * STAGE_BYTES;
#pragma unroll
        for (int it = 0; it < 2; it++) {
            int row = lrow + 64 * it;
            uint32_t so = sbase + row * GPITCH + lkv * 16;
            CP_ASYNC16(so, &gA[(size_t)(mb + row) * GK4 + c * 4 + lkv]);
            CP_ASYNC16(so + SMEM_B_REL, &gB[(size_t)(nb + row) * GK4 + c * 4 + lkv]);
        }
        CP_COMMIT();
    };

    const int NCH = GK4 / 4;   // 32
    load_chunk(0, 0);
    load_chunk(1, 1);

    for (int c = 0; c < NCH; c++) {
        if (c < NCH - 1) CP_WAIT(1);
        else             CP_WAIT(0);
        __syncthreads();
        if (c + 2 < NCH) load_chunk(c + 2, (c + 2) % 3);

        uint32_t sbase = sb + (c % 3) * STAGE_BYTES;
        uint32_t abase = sbase + (wm * 32) * GPITCH;
        uint32_t bbase = sbase + SMEM_B_REL + (wn * 64) * GPITCH;

#pragma unroll
        for (int ks = 0; ks < 2; ks++) {
            uint32_t a_frag[2][4];
            uint32_t b_frag[8][2];
#pragma unroll
            for (int mi = 0; mi < 2; mi++) {
                uint32_t addr = abase + (mi * 16 + (lane & 15)) * GPITCH +
                                ks * 32 + (lane >> 4) * 16;
                ldm_x4(a_frag[mi], addr);
            }
#pragma unroll
            for (int bj = 0; bj < 4; bj++) {
                uint32_t r4[4];
                uint32_t addr = bbase +
                                (bj * 16 + (lane & 7) + ((lane >> 4) & 1) * 8) * GPITCH +
                                ks * 32 + ((lane >> 3) & 1) * 16;
                ldm_x4(r4, addr);
                b_frag[2 * bj][0] = r4[0]; b_frag[2 * bj][1] = r4[1];
                b_frag[2 * bj + 1][0] = r4[2]; b_frag[2 * bj + 1][1] = r4[3];
            }
#pragma unroll
            for (int mi = 0; mi < 2; mi++)
#pragma unroll
                for (int nj = 0; nj < 8; nj++)
                    mma_f16(acc[mi][nj], a_frag[mi], b_frag[nj]);
        }
    }

    const int tq = lane >> 2, tr = lane & 3;
#pragma unroll
    for (int mi = 0; mi < 2; mi++) {
#pragma unroll
        for (int half = 0; half < 2; half++) {
            int row = mb + wm * 32 + mi * 16 + tq + 8 * half;
            if (MODE == 2) {
                int col0 = nb + wn * 64;
                float* yr = (float*)Y0 + (size_t)row * E_DIM + col0;
#pragma unroll
                for (int nj = 0; nj < 8; nj++)
                    *(float2*)&yr[nj * 8 + 2 * tr] =
                        make_float2(acc[mi][nj][2 * half], acc[mi][nj][2 * half + 1]);
            } else {     // MODE 3: QKV fused
                int sel = nb >> 10;
                int col0 = (nb & 1023) + wn * 64;
                __half* yb = (__half*)((sel == 0) ? Y0 : (sel == 1) ? Y1 : Y2);
                __half* yr = yb + (size_t)row * E_DIM + col0;
                int s = row & (S_LEN - 1);
#pragma unroll
                for (int nj = 0; nj < 8; nj++) {
                    float x1 = acc[mi][nj][2 * half];
                    float x2 = acc[mi][nj][2 * half + 1];
                    if (sel < 2) {   // RoPE for q and k
                        int col = col0 + nj * 8 + 2 * tr;
                        float2 cs = tab[s * 32 + ((col >> 1) & 31)];
                        float o1 = x1 * cs.x - x2 * cs.y;
                        float o2 = x2 * cs.x + x1 * cs.y;
                        x1 = o1; x2 = o2;
                    }
                    *(uint32_t*)&yr[nj * 8 + 2 * tr] = f22h(x1, x2);
                }
            }
        }
    }
}

// ============================ flash attention (fp16 HMMA) ==================
// CTA: 256 threads (8 warps), 128 Q rows, K-tiles of 64,
// 4-stage K/V cp.async pipeline, 2 groups in flight.
// Fixed-offset softmax (f32 ex2); warps 0-3 skip their fully-masked final tile.
#define AP 144                       // pitch bytes
#define QTILE (128 * AP)             // 18432
#define KTILE (64 * AP)              // 9216
#define ASMEM (QTILE + 8 * KTILE)    // 92160

__global__ __launch_bounds__(256) void attn_f16(const __half* __restrict__ q,
                                                const __half* __restrict__ k,
                                                const __half* __restrict__ v,
                                                __half* __restrict__ o) {
    extern __shared__ __align__(16) char smA[];
    const uint32_t sQ = smem_u32(smA);
    const uint32_t sK0 = sQ + QTILE;
    const uint32_t sV0 = sQ + QTILE + 4 * KTILE;

    const int tid = threadIdx.x, lane = tid & 31, w = tid >> 5;
    const int bx = gridDim.x - 1 - blockIdx.x;     // heavy CTAs launch first
    const int bh = blockIdx.y;
    const int b = bh >> 4, h = bh & 15;
    const int qbase = bx * 128;
    const size_t bh_off = (size_t)b * S_LEN * E_DIM + (size_t)h * D_HEAD;

#pragma unroll
    for (int i = 0; i < 4; i++) {
        int idx = tid + i * 256;
        int rr = idx >> 3, ch = idx & 7;
        CP_ASYNC16(sQ + rr * AP + ch * 16,
                   (const char*)(q + bh_off + (size_t)(qbase + rr) * E_DIM + ch * 8));
    }
    CP_COMMIT();

    auto load_kv = [&](int kt) {
        int stage = kt & 3;
        uint32_t bK = sK0 + stage * KTILE, bV = sV0 + stage * KTILE;
        int kbase = kt * 64;
#pragma unroll
        for (int i = 0; i < 2; i++) {
            int idx = tid + i * 256;
            int rr = idx >> 3, ch = idx & 7;
            size_t go = bh_off + (size_t)(kbase + rr) * E_DIM + ch * 8;
            CP_ASYNC16(bK + rr * AP + ch * 16, (const char*)(k + go));
            CP_ASYNC16(bV + rr * AP + ch * 16, (const char*)(v + go));
        }
        CP_COMMIT();
    };
    const int ntiles = 2 * bx + 2;    // always >= 2
    load_kv(0);
    load_kv(1);
    if (ntiles > 2) {
        load_kv(2);
        CP_WAIT(3);                    // Q arrived
    } else {
        CP_WAIT(2);
    }
    __syncthreads();

    uint32_t qf[4][4];
    {
        uint32_t a0 = sQ + (16 * w + (lane & 15)) * AP + (lane >> 4) * 16;
#pragma unroll
        for (int dd = 0; dd < 4; dd++) ldm_x4(qf[dd], a0 + dd * 32);
    }

    const int g = lane >> 2, tr = lane & 3;
    const int rg0 = qbase + 16 * w + g;
    const int rg1 = rg0 + 8;

    float l0 = 0.f, l1 = 0.f;       // per-thread partial softmax sums
    float o_[8][4];
#pragma unroll
    for (int j = 0; j < 8; j++)
#pragma unroll
        for (int e = 0; e < 4; e++) o_[j][e] = 0.f;

    for (int kt = 0; kt < ntiles; kt++) {
        int rem = ntiles - 1 - kt;
        if (rem >= 2)      CP_WAIT(2);
        else if (rem == 1) CP_WAIT(1);
        else               CP_WAIT(0);
        __syncthreads();
        if (kt + 3 < ntiles) load_kv(kt + 3);

        // warps 0-3 (rows qbase..qbase+63): final tile is entirely above
        // the diagonal -> skip all compute (loads/barriers still uniform).
        if (w < 4 && kt == ntiles - 1) continue;

        int stage = kt & 3;
        uint32_t bK = sK0 + stage * KTILE, bV = sV0 + stage * KTILE;

        // ---- S = Q K^T ----
        float c[8][4];
#pragma unroll
        for (int j = 0; j < 8; j++)
#pragma unroll
            for (int e = 0; e < 4; e++) c[j][e] = 0.f;

#pragma unroll
        for (int dd = 0; dd < 4; dd++) {
#pragma unroll
            for (int tt = 0; tt < 4; tt++) {
                uint32_t rB[4];
                uint32_t addr = bK +
                    (tt * 16 + (lane & 7) + ((lane >> 4) & 1) * 8) * AP +
                    dd * 32 + ((lane >> 3) & 1) * 16;
                ldm_x4(rB, addr);
                mma_f16(c[2 * tt], qf[dd], rB);
                mma_f16(c[2 * tt + 1], qf[dd], rB + 2);
            }
        }

        // ---- fixed-offset softmax: p = 2^(s*SCALE2 - MOFF) ----
        const bool diag = (kt >= 2 * bx);
        const int kbase = kt * 64;
#pragma unroll
        for (int nj = 0; nj < 8; nj++) {
            int cg = kbase + 8 * nj + 2 * tr;
#pragma unroll
            for (int e = 0; e < 4; e++)
                c[nj][e] = c[nj][e] * SCALE2 - MOFF;   // single FFMA
            if (diag) {
                if (cg     > rg0) c[nj][0] = -1e30f;
                if (cg + 1 > rg0) c[nj][1] = -1e30f;
                if (cg     > rg1) c[nj][2] = -1e30f;
                if (cg + 1 > rg1) c[nj][3] = -1e30f;
            }
            c[nj][0] = ex2(c[nj][0]);
            c[nj][1] = ex2(c[nj][1]);
            c[nj][2] = ex2(c[nj][2]);
            c[nj][3] = ex2(c[nj][3]);
            l0 += c[nj][0] + c[nj][1];
            l1 += c[nj][2] + c[nj][3];
        }

        // ---- P fragments (fp16) ----
        uint32_t pa[4][4];
#pragma unroll
        for (int tk = 0; tk < 4; tk++) {
            pa[tk][0] = f22h(c[2 * tk][0],     c[2 * tk][1]);
            pa[tk][1] = f22h(c[2 * tk][2],     c[2 * tk][3]);
            pa[tk][2] = f22h(c[2 * tk + 1][0], c[2 * tk + 1][1]);
            pa[tk][3] = f22h(c[2 * tk + 1][2], c[2 * tk + 1][3]);
        }

        // ---- O += P V ----
#pragma unroll
        for (int tk = 0; tk < 4; tk++) {
#pragma unroll
            for (int dc = 0; dc < 4; dc++) {
                uint32_t rV[4];
                uint32_t addr = bV +
                    (tk * 16 + (lane & 7) + ((lane >> 3) & 1) * 8) * AP +
                    dc * 32 + ((lane >> 4) & 1) * 16;
                ldm_x4_t(rV, addr);
                mma_f16(o_[2 * dc], pa[tk], rV);
                mma_f16(o_[2 * dc + 1], pa[tk], rV + 2);
            }
        }
    }

    // ---- one-time quad reduction of l, normalize + store f16 ----
    l0 += __shfl_xor_sync(0xFFFFFFFF, l0, 1);
    l0 += __shfl_xor_sync(0xFFFFFFFF, l0, 2);
    l1 += __shfl_xor_sync(0xFFFFFFFF, l1, 1);
    l1 += __shfl_xor_sync(0xFFFFFFFF, l1, 2);
    float il0 = 1.f / l0, il1 = 1.f / l1;
#pragma unroll
    for (int dj = 0; dj < 8; dj++) {
        int d = 8 * dj + 2 * tr;
        *(uint32_t*)&o[bh_off + (size_t)rg0 * E_DIM + d] =
            f22h(o_[dj][0] * il0, o_[dj][1] * il0);
        *(uint32_t*)&o[bh_off + (size_t)rg1 * E_DIM + d] =
            f22h(o_[dj][2] * il1, o_[dj][3] * il1);
    }
}

// ============================ launch =======================================
extern "C" void kernel_launch(void* const* d_in, const int* in_sizes, int n_in,
                              void* d_out, int out_size) {
    const float* x  = (const float*)d_in[0];
    const float* Wq = (const float*)d_in[1];
    const float* Wk = (const float*)d_in[2];
    const float* Wv = (const float*)d_in[3];
    const float* Wo = (const float*)d_in[4];
    float* out = (float*)d_out;

    __half *x16, *wqkv16, *wo16, *q16, *k16, *v16, *a16;
    float2* tab;
    cudaGetSymbolAddress((void**)&x16, g_x16);
    cudaGetSymbolAddress((void**)&wqkv16, g_wqkv16);
    cudaGetSymbolAddress((void**)&wo16, g_wo16);
    cudaGetSymbolAddress((void**)&q16, g_q16);
    cudaGetSymbolAddress((void**)&k16, g_k16);
    cudaGetSymbolAddress((void**)&v16, g_v16);
    cudaGetSymbolAddress((void**)&a16, g_a16);
    cudaGetSymbolAddress((void**)&tab, g_tab);

    cudaFuncSetAttribute(gemm_mma<3>, cudaFuncAttributeMaxDynamicSharedMemorySize, GSMEM);
    cudaFuncSetAttribute(gemm_mma<2>, cudaFuncAttributeMaxDynamicSharedMemorySize, GSMEM);
    cudaFuncSetAttribute(attn_f16, cudaFuncAttributeMaxDynamicSharedMemorySize, ASMEM);

    // one prep launch: x convert + weight converts + rope table
    prep_all<<<4352, 256>>>((const float4*)x,
                            (const float4*)Wq, (const float4*)Wk,
                            (const float4*)Wv, (const float4*)Wo,
                            (uint4*)x16, (uint4*)wqkv16, (uint4*)wo16, tab);

    // fused QKV projection (+RoPE on q,k)
    gemm_mma<3><<<dim3(3 * E_DIM / 128, M_ROWS / 128), 256, GSMEM>>>(
        x16, wqkv16, q16, k16, v16, tab);

    attn_f16<<<dim3(S_LEN / 128, B_SZ * H_NUM), 256, ASMEM>>>(q16, k16, v16, a16);

    // output projection (f32 out)
    gemm_mma<2><<<dim3(E_DIM / 128, M_ROWS / 128), 256, GSMEM>>>(
        a16, wo16, out, nullptr, nullptr, nullptr);
}

// round 17
// speedup vs baseline: 1.1010x; 1.1010x over previous
#include <cuda_runtime.h>
#include <cuda_bf16.h>
#include <cuda_fp16.h>
#include <math.h>
#include <stdint.h>

// Problem constants
#define B_SZ 2
#define S_LEN 2048
#define E_DIM 1024
#define H_NUM 16
#define D_HEAD 64
#define M_ROWS (B_SZ * S_LEN)        // 4096
#define ATTN_SCALE 0.03125f          // 1/sqrt(1024)
#define LOG2E 1.4426950408889634f
#define SCALE2 (ATTN_SCALE * LOG2E)  // base-2 softmax scale
#define MOFF 4.0f                    // fixed softmax offset
#define NLOG2_10K_32 -0.41524101186092029f   // -log2(10000)/32

// ---------------- scratch (device globals: no allocation allowed) ----------
__device__ __half g_x16[M_ROWS * E_DIM];
__device__ __half g_wqkv16[3 * E_DIM * E_DIM];   // concat [Wq; Wk; Wv]
__device__ __half g_wo16[E_DIM * E_DIM];
__device__ __half g_q16[M_ROWS * E_DIM];
__device__ __half g_k16[M_ROWS * E_DIM];
__device__ __half g_v16[M_ROWS * E_DIM];
__device__ __half g_a16[M_ROWS * E_DIM];
__device__ float2 g_tab[S_LEN * 32];               // rope cos/sin table

// ============================ PTX helpers (sm_80-era only) =================
__device__ __forceinline__ uint32_t smem_u32(const void* p) {
    uint32_t a;
    asm("{ .reg .u64 t; cvta.to.shared.u64 t, %1; cvt.u32.u64 %0, t; }"
        : "=r"(a) : "l"(p));
    return a;
}
#define CP_ASYNC16(dst, src) \
    asm volatile("cp.async.cg.shared.global [%0], [%1], 16;" \
                 :: "r"(dst), "l"(src))
#define CP_COMMIT() asm volatile("cp.async.commit_group;")
#define CP_WAIT(n)  asm volatile("cp.async.wait_group %0;" :: "n"(n))

__device__ __forceinline__ void ldm_x4(uint32_t* r, uint32_t addr) {
    asm volatile("ldmatrix.sync.aligned.x4.m8n8.shared.b16 {%0,%1,%2,%3}, [%4];"
                 : "=r"(r[0]), "=r"(r[1]), "=r"(r[2]), "=r"(r[3]) : "r"(addr));
}
__device__ __forceinline__ void ldm_x4_t(uint32_t* r, uint32_t addr) {
    asm volatile("ldmatrix.sync.aligned.x4.m8n8.trans.shared.b16 {%0,%1,%2,%3}, [%4];"
                 : "=r"(r[0]), "=r"(r[1]), "=r"(r[2]), "=r"(r[3]) : "r"(addr));
}
__device__ __forceinline__ void mma_f16(float* d, const uint32_t* a,
                                        const uint32_t* b) {
    asm volatile(
        "mma.sync.aligned.m16n8k16.row.col.f32.f16.f16.f32 "
        "{%0,%1,%2,%3}, {%4,%5,%6,%7}, {%8,%9}, {%0,%1,%2,%3};"
        : "+f"(d[0]), "+f"(d[1]), "+f"(d[2]), "+f"(d[3])
        : "r"(a[0]), "r"(a[1]), "r"(a[2]), "r"(a[3]), "r"(b[0]), "r"(b[1]));
}
__device__ __forceinline__ uint32_t f22h(float a, float b) {
    __half2 h = __floats2half2_rn(a, b);
    return *(uint32_t*)&h;
}
// guaranteed single-MUFU exponential (base 2), f32
__device__ __forceinline__ float ex2(float x) {
    float r;
    asm("ex2.approx.ftz.f32 %0, %1;" : "=f"(r) : "f"(x));
    return r;
}

// ============================ fused prep kernel (all fp32) =================
// blocks [0, 2048)    : convert x -> f16            (4M elems)
// blocks [2048, 4096) : convert Wq/Wk/Wv/Wo -> f16  (4 x 1M elems)
// blocks [4096, 4352) : rope cos/sin table (fp32)   (64K entries)
__global__ __launch_bounds__(256) void prep_all(
    const float4* __restrict__ x,
    const float4* __restrict__ wq, const float4* __restrict__ wk,
    const float4* __restrict__ wv, const float4* __restrict__ wo,
    uint4* __restrict__ ox, uint4* __restrict__ oqkv, uint4* __restrict__ oo,
    float2* __restrict__ tab) {
    int bid = blockIdx.x;
    if (bid < 2048) {                  // x convert
        int idx = bid * 256 + threadIdx.x;
        float4 a = x[2 * idx], b = x[2 * idx + 1];
        uint4 o;
        o.x = f22h(a.x, a.y); o.y = f22h(a.z, a.w);
        o.z = f22h(b.x, b.y); o.w = f22h(b.z, b.w);
        ox[idx] = o;
    } else if (bid < 4096) {           // weight converts
        int idx = (bid - 2048) * 256 + threadIdx.x;   // 4 * 131072
        int sel = idx >> 17;
        int j = idx & 131071;
        const float4* in = (sel == 0) ? wq : (sel == 1) ? wk : (sel == 2) ? wv : wo;
        uint4* out = (sel == 3) ? oo : (oqkv + (size_t)sel * 131072);
        float4 a = in[2 * j], b = in[2 * j + 1];
        uint4 o;
        o.x = f22h(a.x, a.y); o.y = f22h(a.z, a.w);
        o.z = f22h(b.x, b.y); o.w = f22h(b.z, b.w);
        out[j] = o;
    } else {                           // rope table, fp32 (error << budget)
        int idx = (bid - 4096) * 256 + threadIdx.x;   // 65536
        int s = idx >> 5, i = idx & 31;
        float inv = exp2f((float)i * NLOG2_10K_32);
        float cs, sn;
        sincosf((float)s * inv, &sn, &cs);
        tab[idx] = make_float2(cs, sn);
    }
}

// ============================ mma.sync GEMM (R9 calibrated core) ===========
// 128x128 CTA tile, BK=32, 8 warps of 32(M)x64(N), 3-stage cp.async,
// CP_WAIT(1).  MODE 3: QKV fused (f16 + RoPE), MODE 2: f32 out.
#define GPITCH 80
#define STAGE_BYTES (2 * 128 * GPITCH)       // 20480
#define SMEM_B_REL (128 * GPITCH)            // 10240
#define GSMEM (3 * STAGE_BYTES)              // 61440
#define GK4 128                              // uint4 per row (K=1024)

template <int MODE>
__global__ __launch_bounds__(256, 2) void gemm_mma(const void* __restrict__ Av,
                                                   const void* __restrict__ Bv,
                                                   void* __restrict__ Y0,
                                                   void* __restrict__ Y1,
                                                   void* __restrict__ Y2,
                                                   const float2* __restrict__ tab) {
    extern __shared__ __align__(16) char smbuf[];
    const uint32_t sb = smem_u32(smbuf);

    const int tid = threadIdx.x;
    const int wid = tid >> 5, lane = tid & 31;
    const int wm = wid & 3, wn = wid >> 2;
    const int mb = blockIdx.y * 128, nb = blockIdx.x * 128;

    const int lrow = tid >> 2;
    const int lkv = tid & 3;

    float acc[2][8][4];
#pragma unroll
    for (int i = 0; i < 2; i++)
#pragma unroll
        for (int j = 0; j < 8; j++)
#pragma unroll
            for (int q = 0; q < 4; q++) acc[i][j][q] = 0.f;

    const uint4* gA = (const uint4*)Av;
    const uint4* gB = (const uint4*)Bv;

    auto load_chunk = [&](int c, int s) {
        uint32_t sbase = sb + s * STAGE_BYTES;
#pragma unroll
        for (int it = 0; it < 2; it++) {
            int row = lrow + 64 * it;
            uint32_t so = sbase + row * GPITCH + lkv * 16;
            CP_ASYNC16(so, &gA[(size_t)(mb + row) * GK4 + c * 4 + lkv]);
            CP_ASYNC16(so + SMEM_B_REL, &gB[(size_t)(nb + row) * GK4 + c * 4 + lkv]);
        }
        CP_COMMIT();
    };

    const int NCH = GK4 / 4;   // 32
    load_chunk(0, 0);
    load_chunk(1, 1);

    for (int c = 0; c < NCH; c++) {
        if (c < NCH - 1) CP_WAIT(1);
        else             CP_WAIT(0);
        __syncthreads();
        if (c + 2 < NCH) load_chunk(c + 2, (c + 2) % 3);

        uint32_t sbase = sb + (c % 3) * STAGE_BYTES;
        uint32_t abase = sbase + (wm * 32) * GPITCH;
        uint32_t bbase = sbase + SMEM_B_REL + (wn * 64) * GPITCH;

#pragma unroll
        for (int ks = 0; ks < 2; ks++) {
            uint32_t a_frag[2][4];
            uint32_t b_frag[8][2];
#pragma unroll
            for (int mi = 0; mi < 2; mi++) {
                uint32_t addr = abase + (mi * 16 + (lane & 15)) * GPITCH +
                                ks * 32 + (lane >> 4) * 16;
                ldm_x4(a_frag[mi], addr);
            }
#pragma unroll
            for (int bj = 0; bj < 4; bj++) {
                uint32_t r4[4];
                uint32_t addr = bbase +
                                (bj * 16 + (lane & 7) + ((lane >> 4) & 1) * 8) * GPITCH +
                                ks * 32 + ((lane >> 3) & 1) * 16;
                ldm_x4(r4, addr);
                b_frag[2 * bj][0] = r4[0]; b_frag[2 * bj][1] = r4[1];
                b_frag[2 * bj + 1][0] = r4[2]; b_frag[2 * bj + 1][1] = r4[3];
            }
#pragma unroll
            for (int mi = 0; mi < 2; mi++)
#pragma unroll
                for (int nj = 0; nj < 8; nj++)
                    mma_f16(acc[mi][nj], a_frag[mi], b_frag[nj]);
        }
    }

    const int tq = lane >> 2, tr = lane & 3;
#pragma unroll
    for (int mi = 0; mi < 2; mi++) {
#pragma unroll
        for (int half = 0; half < 2; half++) {
            int row = mb + wm * 32 + mi * 16 + tq + 8 * half;
            if (MODE == 2) {
                int col0 = nb + wn * 64;
                float* yr = (float*)Y0 + (size_t)row * E_DIM + col0;
#pragma unroll
                for (int nj = 0; nj < 8; nj++)
                    *(float2*)&yr[nj * 8 + 2 * tr] =
                        make_float2(acc[mi][nj][2 * half], acc[mi][nj][2 * half + 1]);
            } else {     // MODE 3: QKV fused
                int sel = nb >> 10;
                int col0 = (nb & 1023) + wn * 64;
                __half* yb = (__half*)((sel == 0) ? Y0 : (sel == 1) ? Y1 : Y2);
                __half* yr = yb + (size_t)row * E_DIM + col0;
                int s = row & (S_LEN - 1);
#pragma unroll
                for (int nj = 0; nj < 8; nj++) {
                    float x1 = acc[mi][nj][2 * half];
                    float x2 = acc[mi][nj][2 * half + 1];
                    if (sel < 2) {   // RoPE for q and k
                        int col = col0 + nj * 8 + 2 * tr;
                        float2 cs = tab[s * 32 + ((col >> 1) & 31)];
                        float o1 = x1 * cs.x - x2 * cs.y;
                        float o2 = x2 * cs.x + x1 * cs.y;
                        x1 = o1; x2 = o2;
                    }
                    *(uint32_t*)&yr[nj * 8 + 2 * tr] = f22h(x1, x2);
                }
            }
        }
    }
}

// ============================ flash attention (fp16 HMMA) ==================
// CTA: 256 threads (8 warps), 128 Q rows, K-tiles of 64,
// 4-stage K/V cp.async pipeline, 2 groups in flight.
// Fixed-offset softmax (f32 ex2); warps 0-3 skip their fully-masked final tile.
#define AP 144                       // pitch bytes
#define QTILE (128 * AP)             // 18432
#define KTILE (64 * AP)              // 9216
#define ASMEM (QTILE + 8 * KTILE)    // 92160

__global__ __launch_bounds__(256) void attn_f16(const __half* __restrict__ q,
                                                const __half* __restrict__ k,
                                                const __half* __restrict__ v,
                                                __half* __restrict__ o) {
    extern __shared__ __align__(16) char smA[];
    const uint32_t sQ = smem_u32(smA);
    const uint32_t sK0 = sQ + QTILE;
    const uint32_t sV0 = sQ + QTILE + 4 * KTILE;

    const int tid = threadIdx.x, lane = tid & 31, w = tid >> 5;
    const int bx = gridDim.x - 1 - blockIdx.x;     // heavy CTAs launch first
    const int bh = blockIdx.y;
    const int b = bh >> 4, h = bh & 15;
    const int qbase = bx * 128;
    const size_t bh_off = (size_t)b * S_LEN * E_DIM + (size_t)h * D_HEAD;

#pragma unroll
    for (int i = 0; i < 4; i++) {
        int idx = tid + i * 256;
        int rr = idx >> 3, ch = idx & 7;
        CP_ASYNC16(sQ + rr * AP + ch * 16,
                   (const char*)(q + bh_off + (size_t)(qbase + rr) * E_DIM + ch * 8));
    }
    CP_COMMIT();

    auto load_kv = [&](int kt) {
        int stage = kt & 3;
        uint32_t bK = sK0 + stage * KTILE, bV = sV0 + stage * KTILE;
        int kbase = kt * 64;
#pragma unroll
        for (int i = 0; i < 2; i++) {
            int idx = tid + i * 256;
            int rr = idx >> 3, ch = idx & 7;
            size_t go = bh_off + (size_t)(kbase + rr) * E_DIM + ch * 8;
            CP_ASYNC16(bK + rr * AP + ch * 16, (const char*)(k + go));
            CP_ASYNC16(bV + rr * AP + ch * 16, (const char*)(v + go));
        }
        CP_COMMIT();
    };
    const int ntiles = 2 * bx + 2;    // always >= 2
    load_kv(0);
    load_kv(1);
    if (ntiles > 2) {
        load_kv(2);
        CP_WAIT(3);                    // Q arrived
    } else {
        CP_WAIT(2);
    }
    __syncthreads();

    uint32_t qf[4][4];
    {
        uint32_t a0 = sQ + (16 * w + (lane & 15)) * AP + (lane >> 4) * 16;
#pragma unroll
        for (int dd = 0; dd < 4; dd++) ldm_x4(qf[dd], a0 + dd * 32);
    }

    const int g = lane >> 2, tr = lane & 3;
    const int rg0 = qbase + 16 * w + g;
    const int rg1 = rg0 + 8;

    float l0 = 0.f, l1 = 0.f;       // per-thread partial softmax sums
    float o_[8][4];
#pragma unroll
    for (int j = 0; j < 8; j++)
#pragma unroll
        for (int e = 0; e < 4; e++) o_[j][e] = 0.f;

    for (int kt = 0; kt < ntiles; kt++) {
        int rem = ntiles - 1 - kt;
        if (rem >= 2)      CP_WAIT(2);
        else if (rem == 1) CP_WAIT(1);
        else               CP_WAIT(0);
        __syncthreads();
        if (kt + 3 < ntiles) load_kv(kt + 3);

        // warps 0-3 (rows qbase..qbase+63): final tile is entirely above
        // the diagonal -> skip all compute (loads/barriers still uniform).
        if (w < 4 && kt == ntiles - 1) continue;

        int stage = kt & 3;
        uint32_t bK = sK0 + stage * KTILE, bV = sV0 + stage * KTILE;

        // ---- S = Q K^T ----
        float c[8][4];
#pragma unroll
        for (int j = 0; j < 8; j++)
#pragma unroll
            for (int e = 0; e < 4; e++) c[j][e] = 0.f;

#pragma unroll
        for (int dd = 0; dd < 4; dd++) {
#pragma unroll
            for (int tt = 0; tt < 4; tt++) {
                uint32_t rB[4];
                uint32_t addr = bK +
                    (tt * 16 + (lane & 7) + ((lane >> 4) & 1) * 8) * AP +
                    dd * 32 + ((lane >> 3) & 1) * 16;
                ldm_x4(rB, addr);
                mma_f16(c[2 * tt], qf[dd], rB);
                mma_f16(c[2 * tt + 1], qf[dd], rB + 2);
            }
        }

        // ---- fixed-offset softmax: p = 2^(s*SCALE2 - MOFF) ----
        const bool diag = (kt >= 2 * bx);
        const int kbase = kt * 64;
#pragma unroll
        for (int nj = 0; nj < 8; nj++) {
            int cg = kbase + 8 * nj + 2 * tr;
#pragma unroll
            for (int e = 0; e < 4; e++)
                c[nj][e] = c[nj][e] * SCALE2 - MOFF;   // single FFMA
            if (diag) {
                if (cg     > rg0) c[nj][0] = -1e30f;
                if (cg + 1 > rg0) c[nj][1] = -1e30f;
                if (cg     > rg1) c[nj][2] = -1e30f;
                if (cg + 1 > rg1) c[nj][3] = -1e30f;
            }
            c[nj][0] = ex2(c[nj][0]);
            c[nj][1] = ex2(c[nj][1]);
            c[nj][2] = ex2(c[nj][2]);
            c[nj][3] = ex2(c[nj][3]);
            l0 += c[nj][0] + c[nj][1];
            l1 += c[nj][2] + c[nj][3];
        }

        // ---- P fragments (fp16) ----
        uint32_t pa[4][4];
#pragma unroll
        for (int tk = 0; tk < 4; tk++) {
            pa[tk][0] = f22h(c[2 * tk][0],     c[2 * tk][1]);
            pa[tk][1] = f22h(c[2 * tk][2],     c[2 * tk][3]);
            pa[tk][2] = f22h(c[2 * tk + 1][0], c[2 * tk + 1][1]);
            pa[tk][3] = f22h(c[2 * tk + 1][2], c[2 * tk + 1][3]);
        }

        // ---- O += P V ----
#pragma unroll
        for (int tk = 0; tk < 4; tk++) {
#pragma unroll
            for (int dc = 0; dc < 4; dc++) {
                uint32_t rV[4];
                uint32_t addr = bV +
                    (tk * 16 + (lane & 7) + ((lane >> 3) & 1) * 8) * AP +
                    dc * 32 + ((lane >> 4) & 1) * 16;
                ldm_x4_t(rV, addr);
                mma_f16(o_[2 * dc], pa[tk], rV);
                mma_f16(o_[2 * dc + 1], pa[tk], rV + 2);
            }
        }
    }

    // ---- one-time quad reduction of l, normalize + store f16 ----
    l0 += __shfl_xor_sync(0xFFFFFFFF, l0, 1);
    l0 += __shfl_xor_sync(0xFFFFFFFF, l0, 2);
    l1 += __shfl_xor_sync(0xFFFFFFFF, l1, 1);
    l1 += __shfl_xor_sync(0xFFFFFFFF, l1, 2);
    float il0 = 1.f / l0, il1 = 1.f / l1;
#pragma unroll
    for (int dj = 0; dj < 8; dj++) {
        int d = 8 * dj + 2 * tr;
        *(uint32_t*)&o[bh_off + (size_t)rg0 * E_DIM + d] =
            f22h(o_[dj][0] * il0, o_[dj][1] * il0);
        *(uint32_t*)&o[bh_off + (size_t)rg1 * E_DIM + d] =
            f22h(o_[dj][2] * il1, o_[dj][3] * il1);
    }
}

// ============================ launch =======================================
extern "C" void kernel_launch(void* const* d_in, const int* in_sizes, int n_in,
                              void* d_out, int out_size) {
    const float* x  = (const float*)d_in[0];
    const float* Wq = (const float*)d_in[1];
    const float* Wk = (const float*)d_in[2];
    const float* Wv = (const float*)d_in[3];
    const float* Wo = (const float*)d_in[4];
    float* out = (float*)d_out;

    __half *x16, *wqkv16, *wo16, *q16, *k16, *v16, *a16;
    float2* tab;
    cudaGetSymbolAddress((void**)&x16, g_x16);
    cudaGetSymbolAddress((void**)&wqkv16, g_wqkv16);
    cudaGetSymbolAddress((void**)&wo16, g_wo16);
    cudaGetSymbolAddress((void**)&q16, g_q16);
    cudaGetSymbolAddress((void**)&k16, g_k16);
    cudaGetSymbolAddress((void**)&v16, g_v16);
    cudaGetSymbolAddress((void**)&a16, g_a16);
    cudaGetSymbolAddress((void**)&tab, g_tab);

    cudaFuncSetAttribute(gemm_mma<3>, cudaFuncAttributeMaxDynamicSharedMemorySize, GSMEM);
    cudaFuncSetAttribute(gemm_mma<2>, cudaFuncAttributeMaxDynamicSharedMemorySize, GSMEM);
    cudaFuncSetAttribute(attn_f16, cudaFuncAttributeMaxDynamicSharedMemorySize, ASMEM);

    // one prep launch: x convert + weight converts + rope table (all fp32)
    prep_all<<<4352, 256>>>((const float4*)x,
                            (const float4*)Wq, (const float4*)Wk,
                            (const float4*)Wv, (const float4*)Wo,
                            (uint4*)x16, (uint4*)wqkv16, (uint4*)wo16, tab);

    // fused QKV projection (+RoPE on q,k)
    gemm_mma<3><<<dim3(3 * E_DIM / 128, M_ROWS / 128), 256, GSMEM>>>(
        x16, wqkv16, q16, k16, v16, tab);

    attn_f16<<<dim3(S_LEN / 128, B_SZ * H_NUM), 256, ASMEM>>>(q16, k16, v16, a16);

    // output projection (f32 out)
    gemm_mma<2><<<dim3(E_DIM / 128, M_ROWS / 128), 256, GSMEM>>>(
        a16, wo16, out, nullptr, nullptr, nullptr);
}